// round 9
// baseline (speedup 1.0000x reference)
#include <cuda_runtime.h>
#include <cuda_bf16.h>
#include <cstdint>

#define VOCAB    50000
#define NQUADS_X 4096                 // x cell-quads (4 cells per warp)
#define GRID     148
#define THREADS  1024                 // 32 warps
#define RQUADS   12500                // vocab row-quads (4 rows each)
#define NCHUNKS  391                  // ceil(12500 / 32)
#define PERIOD   (NCHUNKS + GRID)     // 539 draws per replay
#define TABLE_BYTES (VOCAB * 4)       // 200000 B smem

__device__ float4   g_proj4[RQUADS];  // 16B-aligned projected table
__device__ unsigned g_work;           // steal counter (monotonic, period-aligned)
__device__ unsigned g_bar;            // barrier counter (monotonic)

__global__ void __launch_bounds__(THREADS, 1) fused_kernel(
    const int*   __restrict__ x,
    const float* __restrict__ E,
    const float* __restrict__ W,
    const float* __restrict__ bias,
    float*       __restrict__ out)
{
    extern __shared__ float s_proj[];   // 200000 B table
    __shared__ int s_chunk;

    int tid  = threadIdx.x;
    int lane = tid & 31;
    int wid  = tid >> 5;                 // 0..31
    int gwarp = blockIdx.x * 32 + wid;   // 0..4735

    // ---- prolog: independent loads (hide under ramp / phase A) ----
    int4 t = make_int4(0, 0, 0, 0);
    if (gwarp < NQUADS_X)
        t = reinterpret_cast<const int4*>(x)[gwarp * 32 + lane];
    float bv = bias[0];

    // ================= Phase A: work-stealing proj =================
    {
        const float4* __restrict__ e4 = reinterpret_cast<const float4*>(E);
        const float4* __restrict__ w4 = reinterpret_cast<const float4*>(W);
        float4 wa = w4[lane];
        float4 wb = w4[lane + 32];

        for (;;) {
            __syncthreads();             // protect s_chunk reuse
            if (tid == 0) {
                unsigned old = atomicAdd(&g_work, 1u);
                s_chunk = (int)(old % (unsigned)PERIOD);
            }
            __syncthreads();
            int c = s_chunk;
            if (c >= NCHUNKS) break;     // block-uniform exit

            int q = c * 32 + wid;        // row-quad for this warp
            if (q < RQUADS) {
                int row0 = q * 4;
                float4 r0a = e4[(size_t)(row0 + 0) * 64 + lane];
                float4 r0b = e4[(size_t)(row0 + 0) * 64 + lane + 32];
                float4 r1a = e4[(size_t)(row0 + 1) * 64 + lane];
                float4 r1b = e4[(size_t)(row0 + 1) * 64 + lane + 32];
                float4 r2a = e4[(size_t)(row0 + 2) * 64 + lane];
                float4 r2b = e4[(size_t)(row0 + 2) * 64 + lane + 32];
                float4 r3a = e4[(size_t)(row0 + 3) * 64 + lane];
                float4 r3b = e4[(size_t)(row0 + 3) * 64 + lane + 32];

                float s0 = 0.f, s1 = 0.f, s2 = 0.f, s3 = 0.f;
                s0 = fmaf(r0a.x, wa.x, s0); s0 = fmaf(r0a.y, wa.y, s0);
                s0 = fmaf(r0a.z, wa.z, s0); s0 = fmaf(r0a.w, wa.w, s0);
                s0 = fmaf(r0b.x, wb.x, s0); s0 = fmaf(r0b.y, wb.y, s0);
                s0 = fmaf(r0b.z, wb.z, s0); s0 = fmaf(r0b.w, wb.w, s0);

                s1 = fmaf(r1a.x, wa.x, s1); s1 = fmaf(r1a.y, wa.y, s1);
                s1 = fmaf(r1a.z, wa.z, s1); s1 = fmaf(r1a.w, wa.w, s1);
                s1 = fmaf(r1b.x, wb.x, s1); s1 = fmaf(r1b.y, wb.y, s1);
                s1 = fmaf(r1b.z, wb.z, s1); s1 = fmaf(r1b.w, wb.w, s1);

                s2 = fmaf(r2a.x, wa.x, s2); s2 = fmaf(r2a.y, wa.y, s2);
                s2 = fmaf(r2a.z, wa.z, s2); s2 = fmaf(r2a.w, wa.w, s2);
                s2 = fmaf(r2b.x, wb.x, s2); s2 = fmaf(r2b.y, wb.y, s2);
                s2 = fmaf(r2b.z, wb.z, s2); s2 = fmaf(r2b.w, wb.w, s2);

                s3 = fmaf(r3a.x, wa.x, s3); s3 = fmaf(r3a.y, wa.y, s3);
                s3 = fmaf(r3a.z, wa.z, s3); s3 = fmaf(r3a.w, wa.w, s3);
                s3 = fmaf(r3b.x, wb.x, s3); s3 = fmaf(r3b.y, wb.y, s3);
                s3 = fmaf(r3b.z, wb.z, s3); s3 = fmaf(r3b.w, wb.w, s3);

                #pragma unroll
                for (int o = 16; o > 0; o >>= 1) {
                    s0 += __shfl_xor_sync(0xFFFFFFFFu, s0, o);
                    s1 += __shfl_xor_sync(0xFFFFFFFFu, s1, o);
                    s2 += __shfl_xor_sync(0xFFFFFFFFu, s2, o);
                    s3 += __shfl_xor_sync(0xFFFFFFFFu, s3, o);
                }
                if (lane == 0)
                    g_proj4[q] = make_float4(s0, s1, s2, s3);
            }
        }
    }

    // ============ grid barrier (single wave: 148 blocks, 1/SM) ============
    if (tid == 0) {
        unsigned old;
        asm volatile("atom.add.release.gpu.u32 %0, [%1], %2;"
                     : "=r"(old) : "l"(&g_bar), "r"(1u) : "memory");
        unsigned target = old - (old % (unsigned)GRID) + (unsigned)GRID;
        unsigned cur;
        do {
            asm volatile("ld.acquire.gpu.u32 %0, [%1];"
                         : "=r"(cur) : "l"(&g_bar) : "memory");
        } while (cur < target);
    }
    __syncthreads();

    // ============ Phase B: stage full table (L2-hot), gather, write ============
    {
        float4* s4 = reinterpret_cast<float4*>(s_proj);
        #pragma unroll 4
        for (int i = tid; i < RQUADS; i += THREADS)
            s4[i] = g_proj4[i];
    }
    __syncthreads();

    if (gwarp < NQUADS_X) {
        float s = s_proj[t.x] + s_proj[t.y] + s_proj[t.z] + s_proj[t.w];
        s += __shfl_xor_sync(0xFFFFFFFFu, s, 4);
        s += __shfl_xor_sync(0xFFFFFFFFu, s, 2);
        s += __shfl_xor_sync(0xFFFFFFFFu, s, 1);
        if ((lane & 7) == 0) out[gwarp * 4 + (lane >> 3)] = s + bv;
    }
}

extern "C" void kernel_launch(void* const* d_in, const int* in_sizes, int n_in,
                              void* d_out, int out_size)
{
    const int*   x = (const int*)  d_in[0];
    const float* E = (const float*)d_in[1];
    const float* W = (const float*)d_in[2];
    const float* b = (const float*)d_in[3];
    float* out = (float*)d_out;

    static bool attr_done = false;
    if (!attr_done) {
        cudaFuncSetAttribute(fused_kernel,
                             cudaFuncAttributeMaxDynamicSharedMemorySize,
                             TABLE_BYTES);
        attr_done = true;
    }

    fused_kernel<<<GRID, THREADS, TABLE_BYTES>>>(x, E, W, b, out);
}

// round 10
// speedup vs baseline: 1.2325x; 1.2325x over previous
#include <cuda_runtime.h>
#include <cuda_bf16.h>
#include <cstdint>

#define VOCAB   50000
#define NCELLS  16384
#define NQUADS  4096                 // cell-quads: 4 cells, 32 int4 per quad
#define RQUADS  12500                // vocab row-quads (4 rows each)
#define GBLOCKS 64                   // gather blocks (minimize chip fill traffic)
#define GTHREADS 1024                // 32 warps
#define QPW     2                    // cell-quads per warp: 4096/(64*32)
#define TABLE_BYTES (VOCAB * 4)      // 200000 B

__device__ float4 g_proj4[RQUADS];   // projected table, quad layout

// ---------------------------------------------------------------------------
// Kernel 1: p[v] = dot(E[v,:], W). 4 rows/warp, 8 outstanding LDG.128/thread,
// one STG.128 per warp (quad store). Near the E L2-streaming floor.
// ---------------------------------------------------------------------------
__global__ void __launch_bounds__(256) proj_kernel(
    const float* __restrict__ E,
    const float* __restrict__ W)
{
    int gwarp = (blockIdx.x * blockDim.x + threadIdx.x) >> 5;
    int lane  = threadIdx.x & 31;
    if (gwarp >= RQUADS) return;
    int row0 = gwarp * 4;

    const float4* __restrict__ e4 = reinterpret_cast<const float4*>(E);
    const float4* __restrict__ w4 = reinterpret_cast<const float4*>(W);

    float4 wa = w4[lane];
    float4 wb = w4[lane + 32];

    float4 r0a = e4[(size_t)(row0 + 0) * 64 + lane];
    float4 r0b = e4[(size_t)(row0 + 0) * 64 + lane + 32];
    float4 r1a = e4[(size_t)(row0 + 1) * 64 + lane];
    float4 r1b = e4[(size_t)(row0 + 1) * 64 + lane + 32];
    float4 r2a = e4[(size_t)(row0 + 2) * 64 + lane];
    float4 r2b = e4[(size_t)(row0 + 2) * 64 + lane + 32];
    float4 r3a = e4[(size_t)(row0 + 3) * 64 + lane];
    float4 r3b = e4[(size_t)(row0 + 3) * 64 + lane + 32];

    float s0 = 0.f, s1 = 0.f, s2 = 0.f, s3 = 0.f;
    s0 = fmaf(r0a.x, wa.x, s0); s0 = fmaf(r0a.y, wa.y, s0);
    s0 = fmaf(r0a.z, wa.z, s0); s0 = fmaf(r0a.w, wa.w, s0);
    s0 = fmaf(r0b.x, wb.x, s0); s0 = fmaf(r0b.y, wb.y, s0);
    s0 = fmaf(r0b.z, wb.z, s0); s0 = fmaf(r0b.w, wb.w, s0);

    s1 = fmaf(r1a.x, wa.x, s1); s1 = fmaf(r1a.y, wa.y, s1);
    s1 = fmaf(r1a.z, wa.z, s1); s1 = fmaf(r1a.w, wa.w, s1);
    s1 = fmaf(r1b.x, wb.x, s1); s1 = fmaf(r1b.y, wb.y, s1);
    s1 = fmaf(r1b.z, wb.z, s1); s1 = fmaf(r1b.w, wb.w, s1);

    s2 = fmaf(r2a.x, wa.x, s2); s2 = fmaf(r2a.y, wa.y, s2);
    s2 = fmaf(r2a.z, wa.z, s2); s2 = fmaf(r2a.w, wa.w, s2);
    s2 = fmaf(r2b.x, wb.x, s2); s2 = fmaf(r2b.y, wb.y, s2);
    s2 = fmaf(r2b.z, wb.z, s2); s2 = fmaf(r2b.w, wb.w, s2);

    s3 = fmaf(r3a.x, wa.x, s3); s3 = fmaf(r3a.y, wa.y, s3);
    s3 = fmaf(r3a.z, wa.z, s3); s3 = fmaf(r3a.w, wa.w, s3);
    s3 = fmaf(r3b.x, wb.x, s3); s3 = fmaf(r3b.y, wb.y, s3);
    s3 = fmaf(r3b.z, wb.z, s3); s3 = fmaf(r3b.w, wb.w, s3);

    #pragma unroll
    for (int o = 16; o > 0; o >>= 1) {
        s0 += __shfl_xor_sync(0xFFFFFFFFu, s0, o);
        s1 += __shfl_xor_sync(0xFFFFFFFFu, s1, o);
        s2 += __shfl_xor_sync(0xFFFFFFFFu, s2, o);
        s3 += __shfl_xor_sync(0xFFFFFFFFu, s3, o);
    }
    if (lane == 0)
        g_proj4[gwarp] = make_float4(s0, s1, s2, s3);
}

// ---------------------------------------------------------------------------
// Kernel 2: out[cell] = sum_t p[x[cell,t]] + bias.
// 64 blocks x 1024 threads: chip-wide fill traffic only 12.8 MB (balanced
// against the 128 B/cyc smem write port). x quads prefetched to registers
// BEFORE the fill wait. 2 cell-quads per warp, 8-lane reduce, direct store.
// ---------------------------------------------------------------------------
__global__ void __launch_bounds__(GTHREADS) gather_kernel(
    const int*   __restrict__ x,
    const float* __restrict__ bias,
    float*       __restrict__ out)
{
    extern __shared__ float s_proj[];   // 200000 B

    int tid  = threadIdx.x;
    int lane = tid & 31;
    int wid  = tid >> 5;                       // 0..31
    int q0   = (blockIdx.x * 32 + wid) * QPW;  // first of 2 consecutive quads

    // ---- start the async fill immediately ----
    uint32_t sbase = (uint32_t)__cvta_generic_to_shared(s_proj);
    const float4* __restrict__ g4 = reinterpret_cast<const float4*>(g_proj4);
    #pragma unroll 13
    for (int i = tid; i < RQUADS; i += GTHREADS) {
        asm volatile("cp.async.cg.shared.global [%0], [%1], 16;"
                     :: "r"(sbase + i * 16), "l"(g4 + i));
    }
    asm volatile("cp.async.commit_group;");

    // ---- prefetch tokens + bias while the fill is in flight ----
    const int4* __restrict__ x4 = reinterpret_cast<const int4*>(x);
    int4 ta = x4[(q0 + 0) * 32 + lane];
    int4 tb = x4[(q0 + 1) * 32 + lane];
    float bv = bias[0];

    asm volatile("cp.async.wait_group 0;" ::: "memory");
    __syncthreads();

    // ---- gather + 8-lane reduce, two quads ----
    float sa = s_proj[ta.x] + s_proj[ta.y] + s_proj[ta.z] + s_proj[ta.w];
    float sb = s_proj[tb.x] + s_proj[tb.y] + s_proj[tb.z] + s_proj[tb.w];

    #pragma unroll
    for (int o = 4; o > 0; o >>= 1) {
        sa += __shfl_xor_sync(0xFFFFFFFFu, sa, o);
        sb += __shfl_xor_sync(0xFFFFFFFFu, sb, o);
    }

    if ((lane & 7) == 0) {
        int c = lane >> 3;
        out[(q0 + 0) * 4 + c] = sa + bv;
        out[(q0 + 1) * 4 + c] = sb + bv;
    }
}

extern "C" void kernel_launch(void* const* d_in, const int* in_sizes, int n_in,
                              void* d_out, int out_size)
{
    const int*   x = (const int*)  d_in[0];
    const float* E = (const float*)d_in[1];
    const float* W = (const float*)d_in[2];
    const float* b = (const float*)d_in[3];
    float* out = (float*)d_out;

    static bool attr_done = false;
    if (!attr_done) {
        cudaFuncSetAttribute(gather_kernel,
                             cudaFuncAttributeMaxDynamicSharedMemorySize,
                             TABLE_BYTES);
        attr_done = true;
    }

    // proj: 12500 row-quads, 8 warps/block -> 1563 blocks
    proj_kernel<<<(RQUADS + 7) / 8, 256>>>(E, W);
    // gather: 64 blocks x 1024 threads, 200 KB smem each
    gather_kernel<<<GBLOCKS, GTHREADS, TABLE_BYTES>>>(x, b, out);
}

// round 11
// speedup vs baseline: 1.2356x; 1.0025x over previous
#include <cuda_runtime.h>
#include <cuda_bf16.h>
#include <cstdint>

#define VOCAB   50000
#define NCELLS  16384
#define NQUADS  4096                 // cell-quads: 4 cells, 32 int4 tokens
#define RQUADS  12500                // vocab row-quads in proj
#define GROUPS  8
#define BPG     37
#define GGRID   (GROUPS * BPG)       // 296 blocks = 2 per SM
#define GT      512                  // 16 warps
#define SLICE   6256                 // floats per slice (16B-aligned bases, 8*6256=50048)
#define SLICE4  (SLICE / 4)          // 1564 float4
#define SLICE_BYTES (SLICE * 4)      // 25024 B smem
#define MAXQ    7                    // quads per warp

__device__ __align__(16) float g_proj[GROUPS * SLICE];   // 50048 (padded)

// ---------------------------------------------------------------------------
// Kernel 1: p[v] = dot(E[v,:], W). 4 rows/warp, 8 outstanding LDG.128/thread,
// one STG.128 per row-quad. Blocks 0..63 also zero out[] for the atomics.
// ---------------------------------------------------------------------------
__global__ void __launch_bounds__(256) proj_kernel(
    const float* __restrict__ E,
    const float* __restrict__ W,
    float*       __restrict__ out)
{
    int gwarp = (blockIdx.x * blockDim.x + threadIdx.x) >> 5;
    int lane  = threadIdx.x & 31;

    if (blockIdx.x < 64)
        out[blockIdx.x * 256 + threadIdx.x] = 0.0f;

    if (gwarp >= RQUADS) return;
    int row0 = gwarp * 4;

    const float4* __restrict__ e4 = reinterpret_cast<const float4*>(E);
    const float4* __restrict__ w4 = reinterpret_cast<const float4*>(W);

    float4 wa = w4[lane];
    float4 wb = w4[lane + 32];

    float4 r0a = e4[(size_t)(row0 + 0) * 64 + lane];
    float4 r0b = e4[(size_t)(row0 + 0) * 64 + lane + 32];
    float4 r1a = e4[(size_t)(row0 + 1) * 64 + lane];
    float4 r1b = e4[(size_t)(row0 + 1) * 64 + lane + 32];
    float4 r2a = e4[(size_t)(row0 + 2) * 64 + lane];
    float4 r2b = e4[(size_t)(row0 + 2) * 64 + lane + 32];
    float4 r3a = e4[(size_t)(row0 + 3) * 64 + lane];
    float4 r3b = e4[(size_t)(row0 + 3) * 64 + lane + 32];

    float s0 = 0.f, s1 = 0.f, s2 = 0.f, s3 = 0.f;
    s0 = fmaf(r0a.x, wa.x, s0); s0 = fmaf(r0a.y, wa.y, s0);
    s0 = fmaf(r0a.z, wa.z, s0); s0 = fmaf(r0a.w, wa.w, s0);
    s0 = fmaf(r0b.x, wb.x, s0); s0 = fmaf(r0b.y, wb.y, s0);
    s0 = fmaf(r0b.z, wb.z, s0); s0 = fmaf(r0b.w, wb.w, s0);

    s1 = fmaf(r1a.x, wa.x, s1); s1 = fmaf(r1a.y, wa.y, s1);
    s1 = fmaf(r1a.z, wa.z, s1); s1 = fmaf(r1a.w, wa.w, s1);
    s1 = fmaf(r1b.x, wb.x, s1); s1 = fmaf(r1b.y, wb.y, s1);
    s1 = fmaf(r1b.z, wb.z, s1); s1 = fmaf(r1b.w, wb.w, s1);

    s2 = fmaf(r2a.x, wa.x, s2); s2 = fmaf(r2a.y, wa.y, s2);
    s2 = fmaf(r2a.z, wa.z, s2); s2 = fmaf(r2a.w, wa.w, s2);
    s2 = fmaf(r2b.x, wb.x, s2); s2 = fmaf(r2b.y, wb.y, s2);
    s2 = fmaf(r2b.z, wb.z, s2); s2 = fmaf(r2b.w, wb.w, s2);

    s3 = fmaf(r3a.x, wa.x, s3); s3 = fmaf(r3a.y, wa.y, s3);
    s3 = fmaf(r3a.z, wa.z, s3); s3 = fmaf(r3a.w, wa.w, s3);
    s3 = fmaf(r3b.x, wb.x, s3); s3 = fmaf(r3b.y, wb.y, s3);
    s3 = fmaf(r3b.z, wb.z, s3); s3 = fmaf(r3b.w, wb.w, s3);

    #pragma unroll
    for (int o = 16; o > 0; o >>= 1) {
        s0 += __shfl_xor_sync(0xFFFFFFFFu, s0, o);
        s1 += __shfl_xor_sync(0xFFFFFFFFu, s1, o);
        s2 += __shfl_xor_sync(0xFFFFFFFFu, s2, o);
        s3 += __shfl_xor_sync(0xFFFFFFFFu, s3, o);
    }
    if (lane == 0)
        reinterpret_cast<float4*>(g_proj)[gwarp] = make_float4(s0, s1, s2, s3);
}

// ---------------------------------------------------------------------------
// Kernel 2: sliced gather. 296 blocks = 8 groups x 37. Group g stages only
// vocab slice [g*6256, (g+1)*6256) = 25 KB smem (1564 cp.async ops). Each
// quad is visited once per group; out-of-slice tokens predicate off; per-cell
// partials accumulate via spread-address atomicAdd. No PDL, no barrier.
// ---------------------------------------------------------------------------
__global__ void __launch_bounds__(GT, 2) gather_kernel(
    const int*   __restrict__ x,
    const float* __restrict__ bias,
    float*       __restrict__ out)
{
    extern __shared__ float s_slice[];   // 25024 B

    int tid  = threadIdx.x;
    int lane = tid & 31;
    int wid  = tid >> 5;                 // 0..15
    int grp  = blockIdx.x / BPG;         // 0..7
    int j    = blockIdx.x % BPG;         // 0..36
    int base = grp * SLICE;

    // ---- start the 25 KB slice fill immediately ----
    uint32_t sbase = (uint32_t)__cvta_generic_to_shared(s_slice);
    const float4* __restrict__ g4 =
        reinterpret_cast<const float4*>(g_proj) + grp * SLICE4;
    #pragma unroll 4
    for (int i = tid; i < SLICE4; i += GT) {
        asm volatile("cp.async.cg.shared.global [%0], [%1], 16;"
                     :: "r"(sbase + i * 16), "l"(g4 + i));
    }
    asm volatile("cp.async.commit_group;");

    // ---- prefetch this block's x quads + bias under the fill ----
    const int4* __restrict__ x4 = reinterpret_cast<const int4*>(x);
    int4 tq[MAXQ];
    #pragma unroll
    for (int i = 0; i < MAXQ; ++i) {
        int q = j + BPG * (wid + 16 * i);
        if (q < NQUADS) tq[i] = x4[q * 32 + lane];
    }
    float bv = (grp == 0) ? bias[0] : 0.0f;

    asm volatile("cp.async.wait_group 0;" ::: "memory");
    __syncthreads();

    // ---- gather in-slice tokens, 8-lane reduce, atomic accumulate ----
    #pragma unroll
    for (int i = 0; i < MAXQ; ++i) {
        int q = j + BPG * (wid + 16 * i);
        if (q >= NQUADS) break;          // monotonic in i

        int4 t = tq[i];
        float s = 0.0f;
        unsigned i0 = (unsigned)(t.x - base);
        unsigned i1 = (unsigned)(t.y - base);
        unsigned i2 = (unsigned)(t.z - base);
        unsigned i3 = (unsigned)(t.w - base);
        if (i0 < (unsigned)SLICE) s += s_slice[i0];
        if (i1 < (unsigned)SLICE) s += s_slice[i1];
        if (i2 < (unsigned)SLICE) s += s_slice[i2];
        if (i3 < (unsigned)SLICE) s += s_slice[i3];

        s += __shfl_xor_sync(0xFFFFFFFFu, s, 4);
        s += __shfl_xor_sync(0xFFFFFFFFu, s, 2);
        s += __shfl_xor_sync(0xFFFFFFFFu, s, 1);

        if ((lane & 7) == 0)
            atomicAdd(&out[q * 4 + (lane >> 3)], s + bv);
    }
}

extern "C" void kernel_launch(void* const* d_in, const int* in_sizes, int n_in,
                              void* d_out, int out_size)
{
    const int*   x = (const int*)  d_in[0];
    const float* E = (const float*)d_in[1];
    const float* W = (const float*)d_in[2];
    const float* b = (const float*)d_in[3];
    float* out = (float*)d_out;

    // proj: 12500 row-quads, 8 warps/block -> 1563 blocks (also zeroes out[])
    proj_kernel<<<(RQUADS + 7) / 8, 256>>>(E, W, out);
    // gather: 296 blocks x 512 threads, 25 KB smem slice each
    gather_kernel<<<GGRID, GT, SLICE_BYTES>>>(x, b, out);
}